// round 2
// baseline (speedup 1.0000x reference)
#include <cuda_runtime.h>
#include <cuda_bf16.h>
#include <math.h>

// Problem constants (fixed by setup_inputs)
#define NR 6144          // rows
#define KB 128           // BIT
#define NC 200           // classes
#define NBK 2048         // histogram buckets, width 1/32 over [-32,32)
#define TPB 256

#define UBF 64.0f
#define CCOEF (-0.28719499063341186f)   // (1/16)*ln(1/99)
#define ACOEF 2.0f
#define ALPHAF 0.1f

typedef unsigned long long u64;

// ---------------- device scratch (no cudaMalloc allowed) ----------------
static __device__ float g_uh[(size_t)NR * KB];
static __device__ float g_inner[(size_t)NR * NR];      // ~151 MB
static __device__ int   g_lab[NR];
static __device__ float g_rowPos[NR];
static __device__ float g_rowNeg[NR];
static __device__ float g_rowQ[NR];
static __device__ int   g_valid[NR];

// ---------------- helpers ----------------
__device__ __forceinline__ float block_reduce_f(float v, float* buf) {
    int t = threadIdx.x;
    __syncthreads();
    buf[t] = v;
    __syncthreads();
    for (int s = TPB / 2; s > 0; s >>= 1) {
        if (t < s) buf[t] += buf[t + s];
        __syncthreads();
    }
    return buf[0];
}

__device__ __forceinline__ int block_reduce_i(int v, int* buf) {
    int t = threadIdx.x;
    __syncthreads();
    buf[t] = v;
    __syncthreads();
    for (int s = TPB / 2; s > 0; s >>= 1) {
        if (t < s) buf[t] += buf[t + s];
        __syncthreads();
    }
    return buf[0];
}

__device__ __forceinline__ float softplus_f(float x) {
    return fmaxf(x, 0.0f) + log1pf(expf(-fabsf(x)));
}

__device__ __forceinline__ int bucket_of(float v) {
    int b = (int)floorf((v + 32.0f) * 32.0f);
    return min(max(b, 0), NBK - 1);
}

// packed fp32x2 FMA (Blackwell FFMA2; only reachable via explicit PTX)
__device__ __forceinline__ u64 ffma2(u64 a, u64 b, u64 c) {
    u64 d;
    asm("fma.rn.f32x2 %0, %1, %2, %3;" : "=l"(d) : "l"(a), "l"(b), "l"(c));
    return d;
}

__device__ __forceinline__ u64 packf2(float lo, float hi) {
    return ((u64)__float_as_uint(hi) << 32) | (u64)__float_as_uint(lo);
}

// ---------------- 1) tanh + labels + quantization partial ----------------
__global__ void prep_kernel(const float* __restrict__ u, const int* __restrict__ y) {
    int row = blockIdx.x;
    int t = threadIdx.x;   // 128 threads
    float uh = tanhf(u[row * KB + t]);
    g_uh[(size_t)row * KB + t] = uh;
    float sg = (uh > 0.0f) ? 1.0f : ((uh < 0.0f) ? -1.0f : 0.0f);
    float d = uh - sg;
    float q = d * d;
    for (int j = t; j < NC; j += KB)
        if (y[row * NC + j] == 1) g_lab[row] = j;
    __shared__ float buf[KB];
    buf[t] = q;
    __syncthreads();
    for (int s = KB / 2; s > 0; s >>= 1) {
        if (t < s) buf[t] += buf[t + s];
        __syncthreads();
    }
    if (t == 0) g_rowQ[row] = buf[0];
}

// ---------------- 2) inner = uh @ uh^T (symmetric, k-pair packed FFMA2) ----------------
// 64x64 tile per 256-thread block; smem holds k-pair-packed u64 operands:
// As[kp][r] = (uh[r][2kp], uh[r][2kp+1]) so FFMA2 needs no per-iteration packing.
#define PADU 70   // u64 row stride: 16B-aligned rows, 2-way-max store conflicts
__global__ void __launch_bounds__(256) gemm_kernel() {
    int bx = blockIdx.x;   // col tile
    int by = blockIdx.y;   // row tile
    if (bx < by) return;

    __shared__ __align__(16) char smraw[2 * 16 * PADU * 8];   // 17.9 KB
    u64 (*As)[PADU] = (u64 (*)[PADU])smraw;
    u64 (*Bs)[PADU] = (u64 (*)[PADU])(smraw + 16 * PADU * 8);

    int tid = threadIdx.x;
    int tx = tid & 15, ty = tid >> 4;
    int rowBase = by * 64, colBase = bx * 64;

    u64 acc[4][4];
#pragma unroll
    for (int i = 0; i < 4; i++)
#pragma unroll
        for (int j = 0; j < 4; j++) acc[i][j] = 0ull;

    for (int kc = 0; kc < 4; kc++) {
#pragma unroll
        for (int l = 0; l < 2; l++) {
            int idx = tid + l * 256;          // 0..511
            int r = idx >> 3;                 // 0..63
            int q = idx & 7;                  // 0..7 (float4 chunk -> 2 k-pairs)
            const float4 fa = *(const float4*)&g_uh[(size_t)(rowBase + r) * KB + kc * 32 + q * 4];
            As[q * 2 + 0][r] = packf2(fa.x, fa.y);
            As[q * 2 + 1][r] = packf2(fa.z, fa.w);
            const float4 fb = *(const float4*)&g_uh[(size_t)(colBase + r) * KB + kc * 32 + q * 4];
            Bs[q * 2 + 0][r] = packf2(fb.x, fb.y);
            Bs[q * 2 + 1][r] = packf2(fb.z, fb.w);
        }
        __syncthreads();
#pragma unroll
        for (int kp = 0; kp < 16; kp++) {
            ulonglong2 aA = *(const ulonglong2*)&As[kp][ty * 4 + 0];
            ulonglong2 aB = *(const ulonglong2*)&As[kp][ty * 4 + 2];
            ulonglong2 bA = *(const ulonglong2*)&Bs[kp][tx * 4 + 0];
            ulonglong2 bB = *(const ulonglong2*)&Bs[kp][tx * 4 + 2];
            u64 a_[4] = {aA.x, aA.y, aB.x, aB.y};
            u64 b_[4] = {bA.x, bA.y, bB.x, bB.y};
#pragma unroll
            for (int i = 0; i < 4; i++)
#pragma unroll
                for (int j = 0; j < 4; j++)
                    acc[i][j] = ffma2(a_[i], b_[j], acc[i][j]);
        }
        __syncthreads();
    }

    // horizontal add of (even-k, odd-k) partial sums
    float accf[4][4];
#pragma unroll
    for (int i = 0; i < 4; i++)
#pragma unroll
        for (int j = 0; j < 4; j++) {
            unsigned lo = (unsigned)acc[i][j];
            unsigned hi = (unsigned)(acc[i][j] >> 32);
            accf[i][j] = __uint_as_float(lo) + __uint_as_float(hi);
        }

#pragma unroll
    for (int i = 0; i < 4; i++)
#pragma unroll
        for (int j = 0; j < 4; j++)
            g_inner[(size_t)(rowBase + ty * 4 + i) * NR + colBase + tx * 4 + j] = accf[i][j];

    if (bx != by) {
        // stage transposed tile through shared for coalesced mirror write
        float (*Ct)[65] = (float (*)[65])smraw;   // 64*65*4 = 16.6 KB, fits
        __syncthreads();
#pragma unroll
        for (int i = 0; i < 4; i++)
#pragma unroll
            for (int j = 0; j < 4; j++)
                Ct[tx * 4 + j][ty * 4 + i] = accf[i][j];
        __syncthreads();
        for (int idx = tid; idx < 4096; idx += 256) {
            int rr = idx >> 6, cc = idx & 63;
            g_inner[(size_t)(colBase + rr) * NR + rowBase + cc] = Ct[rr][cc];
        }
    }
}

// ---------------- 3) fused per-row stats + loss (row cached in smem) ----------------
__global__ void __launch_bounds__(TPB) fused_kernel() {
    __shared__ float rowv[NR];               // 24 KB
    __shared__ unsigned char labs[NR];       // 6 KB
    __shared__ unsigned int hist[NBK];       // 8 KB
    __shared__ float simvals[256];           // 1 KB
    __shared__ float bvals[512];             // 2 KB
    __shared__ float redf[TPB];
    __shared__ int redi[TPB];
    __shared__ unsigned int partial[TPB];
    __shared__ unsigned int cumb[TPB];
    __shared__ unsigned int nsim_sh, nb_sh, cntabove_sh;
    __shared__ int bstar_sh;

    int row = blockIdx.x;
    int tid = threadIdx.x;
    size_t base = (size_t)row * NR;

    // load row (vectorized) + labels (narrowed to u8) + init
    for (int i = tid; i < NR / 4; i += TPB) {
        float4 v = *(const float4*)&g_inner[base + (size_t)i * 4];
        *(float4*)&rowv[i * 4] = v;
        int4 lb = *(const int4*)&g_lab[i * 4];
        labs[i * 4 + 0] = (unsigned char)lb.x;
        labs[i * 4 + 1] = (unsigned char)lb.y;
        labs[i * 4 + 2] = (unsigned char)lb.z;
        labs[i * 4 + 3] = (unsigned char)lb.w;
    }
    for (int i = tid; i < NBK; i += TPB) hist[i] = 0u;
    if (tid == 0) { nsim_sh = 0u; nb_sh = 0u; bstar_sh = -1; cntabove_sh = 0u; }
    __syncthreads();

    unsigned char labr = labs[row];
    float sumS = 0.0f, sumDS = 0.0f;

    // pass A: sums, histogram of dissimilar, similar-value collection
    for (int col = tid; col < NR; col += TPB) {
        float v = rowv[col];
        if (labs[col] == labr) {
            unsigned int p = atomicAdd(&nsim_sh, 1u);
            if (p < 256u) simvals[p] = v;
            sumS += v;
        } else {
            sumDS += v;
            atomicAdd(&hist[bucket_of(v)], 1u);
        }
    }
    sumS = block_reduce_f(sumS, redf);
    sumDS = block_reduce_f(sumDS, redf);
    __syncthreads();

    int n_sim = (int)nsim_sh;
    int n_dis = NR - n_sim;
    int k = n_dis - (n_dis * 9) / 10;   // tail count (>=1 when n_dis>=1)

    // locate bucket containing the k-th largest dissimilar value
    {
        const int BPT = NBK / TPB;      // buckets per thread (8)
        int b0 = NBK - 1 - tid * BPT;
        unsigned int pc = 0u;
#pragma unroll
        for (int q = 0; q < BPT; q++) pc += hist[b0 - q];
        partial[tid] = pc;
        __syncthreads();
        if (tid == 0) {
            unsigned int c = 0u;
            for (int t = 0; t < TPB; t++) { cumb[t] = c; c += partial[t]; }
        }
        __syncthreads();
        if (n_dis > 0 && cumb[tid] < (unsigned)k && cumb[tid] + partial[tid] >= (unsigned)k) {
            unsigned int c = cumb[tid];
            for (int q = 0; q < BPT; q++) {
                int b = b0 - q;
                unsigned int h = hist[b];
                if (c + h >= (unsigned)k) { bstar_sh = b; cntabove_sh = c; break; }
                c += h;
            }
        }
        __syncthreads();
    }

    // pass B: sum above threshold bucket, collect boundary-bucket values
    int bstar = bstar_sh;
    float sumAb = 0.0f;
    for (int col = tid; col < NR; col += TPB) {
        if (labs[col] != labr) {
            float v = rowv[col];
            int b = bucket_of(v);
            if (b > bstar) sumAb += v;
            else if (b == bstar) {
                unsigned int p = atomicAdd(&nb_sh, 1u);
                if (p < 512u) bvals[p] = v;
            }
        }
    }
    sumAb = block_reduce_f(sumAb, redf);
    __syncthreads();

    // exact top-r within boundary bucket (O(m^2) rank; ties sum-invariant)
    int cntb = (int)min(nb_sh, 512u);
    int r = k - (int)cntabove_sh;
    float topr = 0.0f;
    for (int i = tid; i < cntb; i += TPB) {
        float v = bvals[i];
        int rank = 0;
        for (int j = 0; j < cntb; j++) {
            float w = bvals[j];
            rank += (w > v) || (w == v && j < i);
        }
        if (rank < r) topr += v;
    }
    topr = block_reduce_f(topr, redf);

    // bottom-m smallest similar values
    int nsim_c = min(n_sim, 256);
    int m = n_sim - (n_sim * 9) / 10;
    float ssum = 0.0f;
    for (int i = tid; i < nsim_c; i += TPB) {
        float v = simvals[i];
        int rank = 0;
        for (int j = 0; j < nsim_c; j++) {
            float w = simvals[j];
            rank += (w < v) || (w == v && j < i);
        }
        if (rank < m) ssum += v;
    }
    ssum = block_reduce_f(ssum, redf);

    // thresholds (stop-gradient scalars in the reference)
    float fns = fmaxf((float)n_sim, 1.0f);
    float fnd = fmaxf((float)n_dis, 1.0f);
    float meanS  = fminf(fmaxf(sumS  / fns, 0.0f), UBF);
    float meanDS = fminf(fmaxf(sumDS / fnd, 0.0f), UBF);
    float dMax = 0.0f;
    if (n_dis > 0)
        dMax = fminf(fmaxf((sumAb + topr) / fmaxf((float)k, 1.0f), 0.0f), UBF);
    float sMin = fminf(fmaxf(ssum / fmaxf((float)m, 1.0f), 0.0f), UBF);
    float BP  = meanS  - (UBF - meanS) / UBF * fabsf(meanS - dMax);
    float BPd = meanDS + meanDS / UBF * fabsf(meanDS - sMin);

    // pass C: softplus losses from the smem row
    float ps = 0.0f, ns = 0.0f;
    int pc = 0, nc = 0;
    for (int col = tid; col < NR; col += TPB) {
        float v = rowv[col];
        if (labs[col] == labr) {
            if (v != BP) {
                float dc = v - BP;
                float f = (v > BP) ? (CCOEF * dc) : (ACOEF * CCOEF * dc);
                ps += softplus_f(f);
                pc++;
            }
        } else {
            if (v != BPd) {
                float dcd = v - BPd;
                float f = (v < BPd) ? (CCOEF * dcd) : (ACOEF * CCOEF * dcd);
                ns += softplus_f(-f);
                nc++;
            }
        }
    }
    ps = block_reduce_f(ps, redf);
    ns = block_reduce_f(ns, redf);
    pc = block_reduce_i(pc, redi);
    nc = block_reduce_i(nc, redi);

    if (tid == 0) {
        int valid = (n_sim > 0 && n_dis > 0) ? 1 : 0;
        float rp = ps / fmaxf((float)pc, 1.0f);
        float rn = ns / fmaxf((float)nc, 1.0f);
        g_rowPos[row] = valid ? rp : 0.0f;
        g_rowNeg[row] = valid ? rn : 0.0f;
        g_valid[row] = valid;
    }
}

// ---------------- 4) final deterministic reduction ----------------
__global__ void __launch_bounds__(TPB) final_kernel(float* __restrict__ out) {
    int tid = threadIdx.x;
    __shared__ float redf[TPB];
    __shared__ int redi[TPB];

    float p = 0.0f, n = 0.0f, q = 0.0f;
    int c = 0;
    for (int i = tid; i < NR; i += TPB) {
        p += g_rowPos[i];
        n += g_rowNeg[i];
        q += g_rowQ[i];
        c += g_valid[i];
    }
    p = block_reduce_f(p, redf);
    n = block_reduce_f(n, redf);
    q = block_reduce_f(q, redf);
    c = block_reduce_i(c, redi);

    if (tid == 0) {
        float cnt = (float)c;
        float posL = (c > 0) ? p / fmaxf(cnt, 1.0f) : 0.0f;
        float navL = (c > 0) ? n / fmaxf(cnt, 1.0f) : 0.0f;
        float qloss = ALPHAF * (q / (float)((size_t)NR * KB));
        out[0] = posL + navL + qloss;
    }
}

// ---------------- launch ----------------
extern "C" void kernel_launch(void* const* d_in, const int* in_sizes, int n_in,
                              void* d_out, int out_size) {
    const float* u = (const float*)d_in[0];
    const int* y = (const int*)d_in[1];
    (void)in_sizes; (void)n_in; (void)out_size;
    float* out = (float*)d_out;

    prep_kernel<<<NR, KB>>>(u, y);
    dim3 g(NR / 64, NR / 64);
    gemm_kernel<<<g, 256>>>();
    fused_kernel<<<NR, TPB>>>();
    final_kernel<<<1, TPB>>>(out);
}